// round 1
// baseline (speedup 1.0000x reference)
#include <cuda_runtime.h>

// Scratch for the column sums s[256] = sum over rows of x. No device allocs
// allowed, so use a __device__ global. Re-zeroed at the start of every
// kernel_launch so CUDA-graph replays are deterministic.
__device__ float g_colsum[256];

__global__ void zero_scratch_kernel() {
    if (threadIdx.x < 256) g_colsum[threadIdx.x] = 0.0f;
}

// x viewed as float4 rows of width 64. blockDim = 256:
//   lane group c = tid & 63  -> float4 column group (covers cols 4c..4c+3)
//   row subgroup r = tid >> 6 (0..3) -> 4 rows per block-iteration.
// Grid-stride over rows, unrolled x4 for MLP.
__global__ void __launch_bounds__(256) colsum_kernel(
    const float4* __restrict__ x4, long nrows)
{
    const int c = threadIdx.x & 63;
    const int rsub = threadIdx.x >> 6;
    const long stride = (long)gridDim.x * 4;
    long row = (long)blockIdx.x * 4 + rsub;

    float4 acc = make_float4(0.f, 0.f, 0.f, 0.f);

    // 4-way unrolled main loop: 4 independent float4 loads in flight per thread.
    for (; row + 3 * stride < nrows; row += 4 * stride) {
        float4 v0 = x4[(row + 0 * stride) * 64 + c];
        float4 v1 = x4[(row + 1 * stride) * 64 + c];
        float4 v2 = x4[(row + 2 * stride) * 64 + c];
        float4 v3 = x4[(row + 3 * stride) * 64 + c];
        acc.x += v0.x + v1.x + v2.x + v3.x;
        acc.y += v0.y + v1.y + v2.y + v3.y;
        acc.z += v0.z + v1.z + v2.z + v3.z;
        acc.w += v0.w + v1.w + v2.w + v3.w;
    }
    for (; row < nrows; row += stride) {
        float4 v = x4[row * 64 + c];
        acc.x += v.x; acc.y += v.y; acc.z += v.z; acc.w += v.w;
    }

    // Combine the 4 row-subgroups within the block.
    __shared__ float4 sh[256];
    sh[threadIdx.x] = acc;
    __syncthreads();

    if (rsub == 0) {
        float4 a = sh[c];
        float4 b = sh[c + 64];
        float4 d = sh[c + 128];
        float4 e = sh[c + 192];
        atomicAdd(&g_colsum[c * 4 + 0], a.x + b.x + d.x + e.x);
        atomicAdd(&g_colsum[c * 4 + 1], a.y + b.y + d.y + e.y);
        atomicAdd(&g_colsum[c * 4 + 2], a.z + b.z + d.z + e.z);
        atomicAdd(&g_colsum[c * 4 + 3], a.w + b.w + d.w + e.w);
    }
}

// h[o] = dot(s, W[o]) for o in [0,128). One warp per output.
__global__ void gemv_kernel(const float* __restrict__ W, float* __restrict__ out) {
    int warp = (blockIdx.x * blockDim.x + threadIdx.x) >> 5;
    int lane = threadIdx.x & 31;
    if (warp >= 128) return;

    float sum = 0.f;
    #pragma unroll
    for (int i = lane; i < 256; i += 32)
        sum += g_colsum[i] * W[warp * 256 + i];

    #pragma unroll
    for (int off = 16; off; off >>= 1)
        sum += __shfl_xor_sync(0xFFFFFFFFu, sum, off);

    if (lane == 0) out[warp] = sum;
}

extern "C" void kernel_launch(void* const* d_in, const int* in_sizes, int n_in,
                              void* d_out, int out_size) {
    const float* x = (const float*)d_in[0];   // [rows, 256]
    const float* W = (const float*)d_in[1];   // [128, 256]
    float* out = (float*)d_out;               // [1, 128]

    long nrows = (long)in_sizes[0] / 256;

    zero_scratch_kernel<<<1, 256>>>();

    int grid = 1184;  // 148 SMs * 8 blocks
    colsum_kernel<<<grid, 256>>>((const float4*)x, nrows);

    // 128 warps for 128 outputs: 16 blocks * 256 threads = 128 warps.
    gemv_kernel<<<16, 256>>>(W, out);
}

// round 2
// speedup vs baseline: 1.1872x; 1.1872x over previous
#include <cuda_runtime.h>

// Column sums s[256] = sum over rows of x, accumulated by all blocks via
// atomicAdd. The LAST block (atomic counter) computes the 128-output GEMV,
// then zeroes g_colsum and resets the counter so CUDA-graph replays see
// identical initial state. No allocs, one kernel, one graph node.
__device__ float g_colsum[256];
__device__ unsigned int g_done_ctr = 0;

#define GRID   592          // 148 SMs * 4 CTAs
#define BLOCK  256
#define UNROLL 8

__global__ void __launch_bounds__(BLOCK) encoder_fused_kernel(
    const float4* __restrict__ x4, long n4,
    const float* __restrict__ W, float* __restrict__ out)
{
    const int tid = threadIdx.x;
    const long T = (long)GRID * BLOCK;           // total threads
    long idx = (long)blockIdx.x * BLOCK + tid;   // flat float4 index
    // column group is invariant along the grid-stride walk: (idx + k*T) % 64
    // is constant because T % 64 == 0.
    const int c = (int)(idx & 63);               // float4 column group 0..63

    float4 acc = make_float4(0.f, 0.f, 0.f, 0.f);

    // ---- main stream: 8 independent LDG.128 in flight, streaming hint ----
    long i = idx;
    const long chunk = (long)UNROLL * T;
    for (; i + (UNROLL - 1) * T < n4; i += chunk) {
        float4 v0 = __ldcs(&x4[i + 0 * T]);
        float4 v1 = __ldcs(&x4[i + 1 * T]);
        float4 v2 = __ldcs(&x4[i + 2 * T]);
        float4 v3 = __ldcs(&x4[i + 3 * T]);
        float4 v4 = __ldcs(&x4[i + 4 * T]);
        float4 v5 = __ldcs(&x4[i + 5 * T]);
        float4 v6 = __ldcs(&x4[i + 6 * T]);
        float4 v7 = __ldcs(&x4[i + 7 * T]);
        acc.x += (v0.x + v1.x) + (v2.x + v3.x) + ((v4.x + v5.x) + (v6.x + v7.x));
        acc.y += (v0.y + v1.y) + (v2.y + v3.y) + ((v4.y + v5.y) + (v6.y + v7.y));
        acc.z += (v0.z + v1.z) + (v2.z + v3.z) + ((v4.z + v5.z) + (v6.z + v7.z));
        acc.w += (v0.w + v1.w) + (v2.w + v3.w) + ((v4.w + v5.w) + (v6.w + v7.w));
    }
    for (; i < n4; i += T) {
        float4 v = __ldcs(&x4[i]);
        acc.x += v.x; acc.y += v.y; acc.z += v.z; acc.w += v.w;
    }

    // ---- block-level combine: 4 threads share each column group ----
    __shared__ float4 sh[BLOCK];
    sh[tid] = acc;
    __syncthreads();

    if (tid < 64) {
        float4 a = sh[tid];
        float4 b = sh[tid + 64];
        float4 d = sh[tid + 128];
        float4 e = sh[tid + 192];
        // NOTE: c == tid here for tid < 64
        atomicAdd(&g_colsum[tid * 4 + 0], a.x + b.x + d.x + e.x);
        atomicAdd(&g_colsum[tid * 4 + 1], a.y + b.y + d.y + e.y);
        atomicAdd(&g_colsum[tid * 4 + 2], a.z + b.z + d.z + e.z);
        atomicAdd(&g_colsum[tid * 4 + 3], a.w + b.w + d.w + e.w);
    }

    // ---- last-block election ----
    __shared__ int is_last;
    __threadfence();
    __syncthreads();
    if (tid == 0) {
        unsigned int prev = atomicAdd(&g_done_ctr, 1u);
        is_last = (prev == GRID - 1) ? 1 : 0;
    }
    __syncthreads();
    if (!is_last) return;

    // ---- finalize (single block): gemv h[o] = dot(g_colsum, W[o]) ----
    __shared__ float s[256];
    s[tid] = g_colsum[tid];
    __syncthreads();

    // 8 warps * 16 outputs each = 128 outputs
    const int warp = tid >> 5;
    const int lane = tid & 31;
    for (int o = warp * 16; o < warp * 16 + 16; o++) {
        const float* Wrow = W + o * 256;
        float sum = 0.f;
        #pragma unroll
        for (int j = 0; j < 8; j++)
            sum += s[lane + 32 * j] * __ldg(&Wrow[lane + 32 * j]);
        #pragma unroll
        for (int off = 16; off; off >>= 1)
            sum += __shfl_xor_sync(0xFFFFFFFFu, sum, off);
        if (lane == 0) out[o] = sum;
    }
    __syncthreads();

    // ---- reset state for the next graph replay ----
    g_colsum[tid] = 0.0f;
    if (tid == 0) g_done_ctr = 0;
}

extern "C" void kernel_launch(void* const* d_in, const int* in_sizes, int n_in,
                              void* d_out, int out_size) {
    const float* x = (const float*)d_in[0];   // [rows, 256] fp32
    const float* W = (const float*)d_in[1];   // [128, 256] fp32
    float* out = (float*)d_out;               // [1, 128] fp32

    long n4 = (long)in_sizes[0] / 4;          // number of float4 elements

    encoder_fused_kernel<<<GRID, BLOCK>>>((const float4*)x, n4, W, out);
}